// round 3
// baseline (speedup 1.0000x reference)
#include <cuda_runtime.h>
#include <math.h>

#define NB 8
#define NC 256
#define NHW 1024
#define NHEAD 8
#define NHD 32
#define NN 102
#define NGD 64

// ---------------- static device scratch (no allocations allowed) ----------------
static __device__ float d_xs[NB*NHW*NC];          // x transposed: [B, HW, C]
static __device__ float d_imp[NB*NHW];
static __device__ int   d_topidx[NB*NN];
static __device__ int   d_nodeof[NB*NHW];         // hw -> node index or -1
static __device__ float d_feats[NB*NN*NC];
static __device__ float d_normv[NB*NN];
static __device__ unsigned char d_adj[NB*NN*NN];
static __device__ float d_g0[NB*NN*NGD];
static __device__ float d_g1[NB*NN*NGD];
static __device__ float d_gwts[NB*NN*NHEAD];
static __device__ float d_q[NB*NHEAD*NHW*NHD];
static __device__ float d_k[NB*NHEAD*NHW*NHD];
static __device__ float d_v[NB*NHEAD*NHW*NHD];
static __device__ float d_ao[NB*NHW*NC];          // attention output [B, HW, C]

__device__ __forceinline__ float wsum(float v){
  #pragma unroll
  for (int o = 16; o; o >>= 1) v += __shfl_xor_sync(0xffffffffu, v, o);
  return v;
}
__device__ __forceinline__ float wmax(float v){
  #pragma unroll
  for (int o = 16; o; o >>= 1) v = fmaxf(v, __shfl_xor_sync(0xffffffffu, v, o));
  return v;
}

// ---------------- 1) transpose x [B,C,HW] -> xs [B,HW,C] ----------------
__global__ void transpose_kernel(const float* __restrict__ x){
  __shared__ float tile[32][33];
  int b = blockIdx.z;
  int hw0 = blockIdx.x * 32, c0 = blockIdx.y * 32;
  int tx = threadIdx.x, ty = threadIdx.y;
  #pragma unroll
  for (int i = 0; i < 4; i++)
    tile[ty + 8*i][tx] = x[((size_t)b*NC + (c0 + ty + 8*i))*NHW + hw0 + tx];
  __syncthreads();
  #pragma unroll
  for (int i = 0; i < 4; i++)
    d_xs[((size_t)b*NHW + (hw0 + ty + 8*i))*NC + c0 + tx] = tile[tx][ty + 8*i];
}

// ---------------- 2) variance (ddof=1) per (b,hw) ----------------
__global__ void importance_kernel(){
  int row = blockIdx.x * 8 + (threadIdx.x >> 5);      // 8192 rows
  int lane = threadIdx.x & 31;
  const float* p = d_xs + (size_t)row * NC;
  float v[8]; float s = 0.f;
  #pragma unroll
  for (int i = 0; i < 8; i++){ v[i] = p[lane + 32*i]; s += v[i]; }
  s = wsum(s);
  float mean = s * (1.f/256.f);
  float q = 0.f;
  #pragma unroll
  for (int i = 0; i < 8; i++){ float d = v[i] - mean; q += d*d; }
  q = wsum(q);
  if (lane == 0) d_imp[row] = q * (1.f/255.f);
}

// ---------------- 3) per-batch top-102 via bitonic sort ----------------
__global__ __launch_bounds__(1024) void topk_kernel(){
  __shared__ float key[1024];
  __shared__ int   idxv[1024];
  int b = blockIdx.x, tid = threadIdx.x;
  key[tid]  = d_imp[b*NHW + tid];
  idxv[tid] = tid;
  d_nodeof[b*NHW + tid] = -1;
  __syncthreads();
  for (int k = 2; k <= 1024; k <<= 1){
    for (int j = k >> 1; j > 0; j >>= 1){
      int ixj = tid ^ j;
      if (ixj > tid){
        bool desc = ((tid & k) == 0);
        float a = key[tid], bb = key[ixj];
        if (desc ? (a < bb) : (a > bb)){
          key[tid] = bb; key[ixj] = a;
          int t = idxv[tid]; idxv[tid] = idxv[ixj]; idxv[ixj] = t;
        }
      }
      __syncthreads();
    }
  }
  if (tid < NN){
    int src = idxv[tid];
    d_topidx[b*NN + tid] = src;
    d_nodeof[b*NHW + src] = tid;
  }
}

// ---------------- 4) gather node features ----------------
__global__ void gather_kernel(){
  int bi = blockIdx.x;                 // 0..815
  int b = bi / NN;
  int src = d_topidx[bi];
  d_feats[(size_t)bi*NC + threadIdx.x] = d_xs[((size_t)b*NHW + src)*NC + threadIdx.x];
}

// ---------------- 5) row norms ----------------
__global__ void norm_kernel(){
  int row = blockIdx.x * 8 + (threadIdx.x >> 5);      // 816 rows
  int lane = threadIdx.x & 31;
  const float* p = d_feats + (size_t)row * NC;
  float s = 0.f;
  #pragma unroll
  for (int i = 0; i < 8; i++){ float v = p[lane + 32*i]; s += v*v; }
  s = wsum(s);
  if (lane == 0) d_normv[row] = fmaxf(sqrtf(s), 1e-12f);
}

// ---------------- 6) cosine-sim adjacency (+self loops) ----------------
__global__ void adj_kernel(){
  int bi = blockIdx.x;
  int b = bi / NN, i = bi % NN;
  int warp = threadIdx.x >> 5, lane = threadIdx.x & 31;
  const float* fi = d_feats + (size_t)bi * NC;
  float ni = d_normv[bi];
  for (int j = warp; j < NN; j += 4){
    const float* fj = d_feats + ((size_t)b*NN + j) * NC;
    float s = 0.f;
    #pragma unroll
    for (int t = 0; t < 8; t++) s += fi[lane + 32*t] * fj[lane + 32*t];
    s = wsum(s);
    if (lane == 0){
      float sim = s / (ni * d_normv[b*NN + j]);
      d_adj[(size_t)bi*NN + j] = (unsigned char)((sim > 0.6f) || (j == i));
    }
  }
}

// ---------------- 7) GAT layer (one block per batch) ----------------
__global__ __launch_bounds__(256) void gat_kernel(int layer,
    const float* __restrict__ W, const float* __restrict__ aw_src,
    const float* __restrict__ aw_dst, const float* __restrict__ bias){
  __shared__ float h[NN*NGD];
  __shared__ float s_asrc[NN], s_adst[NN];
  __shared__ float alpha[8][104];
  int b = blockIdx.x, tid = threadIdx.x;
  const float* fin = layer ? d_g0 : d_feats;
  float* fout = layer ? d_g1 : d_g0;
  int in_dim = layer ? NGD : NC;
  const float* fb = fin + (size_t)b * NN * in_dim;

  // h = f @ W
  for (int idx = tid; idx < NN*NGD; idx += 256){
    int i = idx >> 6, o = idx & 63;
    const float* fr = fb + (size_t)i * in_dim;
    float s = 0.f;
    for (int c = 0; c < in_dim; c++) s += fr[c] * W[c*NGD + o];
    h[idx] = s;
  }
  __syncthreads();
  if (tid < NN){
    float s1 = 0.f, s2 = 0.f;
    const float* hr = h + tid * NGD;
    #pragma unroll
    for (int o = 0; o < NGD; o++){ float hv = hr[o]; s1 += hv*aw_src[o]; s2 += hv*aw_dst[o]; }
    s_asrc[tid] = s1; s_adst[tid] = s2;
  }
  __syncthreads();

  int warp = tid >> 5, lane = tid & 31;
  const unsigned char* adjb = d_adj + (size_t)b * NN * NN;
  for (int i = warp; i < NN; i += 8){
    float ad = s_adst[i];
    const unsigned char* arow = adjb + (size_t)i * NN;  // adj symmetric -> mask.T == mask
    float mx = -1e30f;
    for (int j = lane; j < NN; j += 32){
      float lg = ad + s_asrc[j];
      lg = lg > 0.f ? lg : 0.2f*lg;                     // LeakyReLU(0.2)
      if (!arow[j]) lg = -1e30f;
      alpha[warp][j] = lg;
      mx = fmaxf(mx, lg);
    }
    mx = wmax(mx);
    float sum = 0.f;
    for (int j = lane; j < NN; j += 32){
      float e = expf(alpha[warp][j] - mx);
      alpha[warp][j] = e;
      sum += e;
    }
    sum = wsum(sum);
    float inv = 1.f / sum;
    float acc0 = 0.f, acc1 = 0.f;
    for (int j = 0; j < NN; j++){
      float a = alpha[warp][j];
      acc0 += a * h[j*NGD + lane];
      acc1 += a * h[j*NGD + lane + 32];
    }
    fout[((size_t)b*NN + i)*NGD + lane]      = fmaxf(acc0*inv + bias[lane],      0.f);
    fout[((size_t)b*NN + i)*NGD + lane + 32] = fmaxf(acc1*inv + bias[lane + 32], 0.f);
  }
}

// ---------------- 8) graph -> attention gates ----------------
__global__ void g2a_kernel(const float* __restrict__ wg, const float* __restrict__ bg){
  int b = blockIdx.x, tid = threadIdx.x;
  for (int idx = tid; idx < NN*NHEAD; idx += 256){
    int i = idx >> 3, hh = idx & 7;
    const float* gr = d_g1 + ((size_t)b*NN + i) * NGD;
    float s = bg[hh];
    #pragma unroll
    for (int o = 0; o < NGD; o++) s += gr[o] * wg[hh*NGD + o];
    d_gwts[((size_t)b*NN + i)*NHEAD + hh] = 1.f / (1.f + expf(-s));
  }
}

// ---------------- 9) QKV GEMM: [8192,256] @ [256,768]^T, scatter epilogue ----------------
__global__ __launch_bounds__(256) void qkv_gemm(const float* __restrict__ Wq){
  __shared__ float As[16][132];
  __shared__ float Bs[16][132];
  int tid = threadIdx.x;
  int tx = tid & 15, ty = tid >> 4;
  int rowBase = blockIdx.y * 128;
  int colBase = blockIdx.x * 128;
  float acc[8][8];
  #pragma unroll
  for (int i = 0; i < 8; i++)
    #pragma unroll
    for (int j = 0; j < 8; j++) acc[i][j] = 0.f;

  for (int k0 = 0; k0 < 256; k0 += 16){
    #pragma unroll
    for (int l = 0; l < 2; l++){
      int t = tid + l*256;
      int row = t >> 2;
      int kq = (t & 3) << 2;
      float4 va = *(const float4*)&d_xs[(size_t)(rowBase + row)*256 + k0 + kq];
      As[kq][row] = va.x; As[kq+1][row] = va.y; As[kq+2][row] = va.z; As[kq+3][row] = va.w;
      float4 vb = *(const float4*)&Wq[(size_t)(colBase + row)*256 + k0 + kq];
      Bs[kq][row] = vb.x; Bs[kq+1][row] = vb.y; Bs[kq+2][row] = vb.z; Bs[kq+3][row] = vb.w;
    }
    __syncthreads();
    #pragma unroll
    for (int kk = 0; kk < 16; kk++){
      float a[8], bb[8];
      #pragma unroll
      for (int i = 0; i < 8; i++) a[i] = As[kk][ty + 16*i];
      #pragma unroll
      for (int j = 0; j < 8; j++) bb[j] = Bs[kk][tx + 16*j];
      #pragma unroll
      for (int i = 0; i < 8; i++)
        #pragma unroll
        for (int j = 0; j < 8; j++) acc[i][j] += a[i]*bb[j];
    }
    __syncthreads();
  }
  #pragma unroll
  for (int i = 0; i < 8; i++){
    int m = rowBase + ty + 16*i;
    int b = m >> 10, hw = m & 1023;
    #pragma unroll
    for (int j = 0; j < 8; j++){
      int o = colBase + tx + 16*j;
      int s = o >> 8, hh = (o >> 5) & 7, dd = o & 31;
      float* dst = (s == 0) ? d_q : (s == 1 ? d_k : d_v);
      dst[(((size_t)(b*8 + hh))*1024 + hw)*32 + dd] = acc[i][j];
    }
  }
}

// ---------------- 10) fused flash attention + graph modulation ----------------
__global__ __launch_bounds__(256) void attn_kernel(){
  __shared__ float Qs[64][36];
  __shared__ float Ks[64][36];
  __shared__ float Vs[64][32];
  __shared__ float Ss[64][68];
  __shared__ float qg[64]; __shared__ int qn[64];
  __shared__ float kg[64]; __shared__ int kn[64];

  int bh = blockIdx.x;
  int b = bh >> 3, h = bh & 7;
  int q0 = blockIdx.y << 6;
  int tid = threadIdx.x;

  const float* Qb = d_q + ((size_t)bh*NHW + q0)*NHD;
  #pragma unroll
  for (int l = 0; l < 2; l++){
    int t = tid + l*256;
    int r = t >> 3, d4 = (t & 7) << 2;
    float4 v = *(const float4*)(Qb + r*NHD + d4);
    Qs[r][d4] = v.x; Qs[r][d4+1] = v.y; Qs[r][d4+2] = v.z; Qs[r][d4+3] = v.w;
  }
  if (tid < 64){
    int iq = d_nodeof[b*NHW + q0 + tid];
    qn[tid] = iq;
    qg[tid] = (iq >= 0) ? d_gwts[((size_t)b*NN + iq)*NHEAD + h] : 0.f;
  }

  const unsigned char* adjb = d_adj + (size_t)b * NN * NN;
  const float scale = 0.17677669529663687f;   // 1/sqrt(32)

  float m = -1e30f, lsumAll = 0.f;
  float oacc[8];
  #pragma unroll
  for (int i = 0; i < 8; i++) oacc[i] = 0.f;
  int rrow = tid >> 2;
  int gl   = tid & 3;
  int d0   = gl << 3;
  int r0   = tid >> 4;
  int c0   = tid & 15;

  for (int kt = 0; kt < 16; kt++){
    __syncthreads();
    const float* Kb = d_k + ((size_t)bh*NHW + kt*64)*NHD;
    const float* Vb = d_v + ((size_t)bh*NHW + kt*64)*NHD;
    #pragma unroll
    for (int l = 0; l < 2; l++){
      int t = tid + l*256;
      int r = t >> 3, d4 = (t & 7) << 2;
      float4 kv = *(const float4*)(Kb + r*NHD + d4);
      Ks[r][d4] = kv.x; Ks[r][d4+1] = kv.y; Ks[r][d4+2] = kv.z; Ks[r][d4+3] = kv.w;
      float4 vv = *(const float4*)(Vb + r*NHD + d4);
      *(float4*)&Vs[r][d4] = vv;
    }
    if (tid < 64){
      int ik = d_nodeof[b*NHW + kt*64 + tid];
      kn[tid] = ik;
      kg[tid] = (ik >= 0) ? d_gwts[((size_t)b*NN + ik)*NHEAD + h] : 0.f;
    }
    __syncthreads();

    // S = Q K^T (4x4 micro-tiles, float4 operands)
    float acc[4][4];
    #pragma unroll
    for (int i = 0; i < 4; i++)
      #pragma unroll
      for (int j = 0; j < 4; j++) acc[i][j] = 0.f;
    #pragma unroll
    for (int d4 = 0; d4 < 32; d4 += 4){
      float4 qa[4], kb[4];
      #pragma unroll
      for (int i = 0; i < 4; i++) qa[i] = *(const float4*)&Qs[r0 + 16*i][d4];
      #pragma unroll
      for (int j = 0; j < 4; j++) kb[j] = *(const float4*)&Ks[c0 + 16*j][d4];
      #pragma unroll
      for (int i = 0; i < 4; i++)
        #pragma unroll
        for (int j = 0; j < 4; j++)
          acc[i][j] += qa[i].x*kb[j].x + qa[i].y*kb[j].y + qa[i].z*kb[j].z + qa[i].w*kb[j].w;
    }
    // scale + graph modulation, store to smem
    #pragma unroll
    for (int i = 0; i < 4; i++){
      int r = r0 + 16*i;
      int iq = qn[r];
      float qgr = qg[r];
      #pragma unroll
      for (int j = 0; j < 4; j++){
        int c = c0 + 16*j;
        float s = acc[i][j] * scale;
        int ik = kn[c];
        if (iq >= 0 && ik >= 0 && adjb[iq*NN + ik]) s += qgr * kg[c];
        Ss[r][c] = s;
      }
    }
    __syncthreads();

    // online softmax (4 lanes per row) + O += P V
    float tmax = -1e30f;
    for (int c = gl; c < 64; c += 4) tmax = fmaxf(tmax, Ss[rrow][c]);
    tmax = fmaxf(tmax, __shfl_xor_sync(0xffffffffu, tmax, 1));
    tmax = fmaxf(tmax, __shfl_xor_sync(0xffffffffu, tmax, 2));
    float mnew = fmaxf(m, tmax);
    float fac = expf(m - mnew);
    float ls = 0.f;
    for (int c = gl; c < 64; c += 4){
      float e = expf(Ss[rrow][c] - mnew);
      Ss[rrow][c] = e;
      ls += e;
    }
    ls += __shfl_xor_sync(0xffffffffu, ls, 1);
    ls += __shfl_xor_sync(0xffffffffu, ls, 2);
    lsumAll = lsumAll * fac + ls;
    m = mnew;
    #pragma unroll
    for (int i = 0; i < 8; i++) oacc[i] *= fac;
    __syncwarp();
    for (int c = 0; c < 64; c++){
      float p = Ss[rrow][c];
      float4 v0 = *(const float4*)&Vs[c][d0];
      float4 v1 = *(const float4*)&Vs[c][d0 + 4];
      oacc[0] += p*v0.x; oacc[1] += p*v0.y; oacc[2] += p*v0.z; oacc[3] += p*v0.w;
      oacc[4] += p*v1.x; oacc[5] += p*v1.y; oacc[6] += p*v1.z; oacc[7] += p*v1.w;
    }
  }
  float inv = 1.f / lsumAll;
  int q = q0 + rrow;
  float* dst = d_ao + ((size_t)(b*NHW + q))*NC + h*NHD + d0;
  float4 o0 = make_float4(oacc[0]*inv, oacc[1]*inv, oacc[2]*inv, oacc[3]*inv);
  float4 o1 = make_float4(oacc[4]*inv, oacc[5]*inv, oacc[6]*inv, oacc[7]*inv);
  *(float4*)dst = o0;
  *(float4*)(dst + 4) = o1;
}

// ---------------- 11) proj GEMM + bias + transposed store ----------------
__global__ __launch_bounds__(256) void proj_gemm(const float* __restrict__ Wp,
    const float* __restrict__ bias, float* __restrict__ out){
  __shared__ float As[16][132];
  __shared__ float Bs[16][132];
  int tid = threadIdx.x;
  int tx = tid & 15, ty = tid >> 4;
  int rowBase = blockIdx.y * 128;
  int colBase = blockIdx.x * 128;
  float acc[8][8];
  #pragma unroll
  for (int i = 0; i < 8; i++)
    #pragma unroll
    for (int j = 0; j < 8; j++) acc[i][j] = 0.f;

  for (int k0 = 0; k0 < 256; k0 += 16){
    #pragma unroll
    for (int l = 0; l < 2; l++){
      int t = tid + l*256;
      int row = t >> 2;
      int kq = (t & 3) << 2;
      float4 va = *(const float4*)&d_ao[(size_t)(rowBase + row)*256 + k0 + kq];
      As[kq][row] = va.x; As[kq+1][row] = va.y; As[kq+2][row] = va.z; As[kq+3][row] = va.w;
      float4 vb = *(const float4*)&Wp[(size_t)(colBase + row)*256 + k0 + kq];
      Bs[kq][row] = vb.x; Bs[kq+1][row] = vb.y; Bs[kq+2][row] = vb.z; Bs[kq+3][row] = vb.w;
    }
    __syncthreads();
    #pragma unroll
    for (int kk = 0; kk < 16; kk++){
      float a[8], bb[8];
      #pragma unroll
      for (int i = 0; i < 8; i++) a[i] = As[kk][ty + 16*i];
      #pragma unroll
      for (int j = 0; j < 8; j++) bb[j] = Bs[kk][tx + 16*j];
      #pragma unroll
      for (int i = 0; i < 8; i++)
        #pragma unroll
        for (int j = 0; j < 8; j++) acc[i][j] += a[i]*bb[j];
    }
    __syncthreads();
  }
  #pragma unroll
  for (int i = 0; i < 8; i++){
    int mI = rowBase + ty + 16*i;
    int b = mI >> 10, hw = mI & 1023;
    #pragma unroll
    for (int j = 0; j < 8; j++){
      int o = colBase + tx + 16*j;
      out[((size_t)(b*NC + o))*NHW + hw] = acc[i][j] + bias[o];
    }
  }
}

// ---------------- launch ----------------
extern "C" void kernel_launch(void* const* d_in, const int* in_sizes, int n_in,
                              void* d_out, int out_size){
  (void)in_sizes; (void)n_in; (void)out_size;
  const float* x      = (const float*)d_in[0];
  const float* w_qkv  = (const float*)d_in[1];
  const float* w_proj = (const float*)d_in[2];
  const float* b_proj = (const float*)d_in[3];
  const float* g0W    = (const float*)d_in[4];
  const float* g0s    = (const float*)d_in[5];
  const float* g0d    = (const float*)d_in[6];
  const float* g0b    = (const float*)d_in[7];
  const float* g1W    = (const float*)d_in[8];
  const float* g1s    = (const float*)d_in[9];
  const float* g1d    = (const float*)d_in[10];
  const float* g1b    = (const float*)d_in[11];
  const float* wg2a   = (const float*)d_in[12];
  const float* bg2a   = (const float*)d_in[13];
  float* out = (float*)d_out;

  transpose_kernel<<<dim3(32, 8, 8), dim3(32, 8)>>>(x);
  importance_kernel<<<1024, 256>>>();
  topk_kernel<<<8, 1024>>>();
  gather_kernel<<<816, 256>>>();
  norm_kernel<<<102, 256>>>();
  adj_kernel<<<816, 128>>>();
  gat_kernel<<<8, 256>>>(0, g0W, g0s, g0d, g0b);
  gat_kernel<<<8, 256>>>(1, g1W, g1s, g1d, g1b);
  g2a_kernel<<<8, 256>>>(wg2a, bg2a);
  qkv_gemm<<<dim3(6, 64), 256>>>(w_qkv);
  attn_kernel<<<dim3(64, 16), 256>>>();
  proj_gemm<<<dim3(2, 64), 256>>>(w_proj, b_proj, out);
}

// round 5
// speedup vs baseline: 4.0409x; 4.0409x over previous
#include <cuda_runtime.h>
#include <math.h>

#define NB 8
#define NC 256
#define NHW 1024
#define NHEAD 8
#define NHD 32
#define NN 102
#define NGD 64

// ---------------- static device scratch ----------------
static __device__ float d_xs[NB*NHW*NC];          // x transposed: [B, HW, C]
static __device__ float d_imp[NB*NHW];
static __device__ int   d_topidx[NB*NN];
static __device__ int   d_nodeof[NB*NHW];         // hw -> node index or -1
static __device__ float d_feats[NB*NN*NC];
static __device__ float d_normv[NB*NN];
static __device__ unsigned char d_adj[NB*NN*NN];
static __device__ float d_h[NB*NN*NGD];           // GAT pre-aggregation features
static __device__ float d_asrc[NB*NN];
static __device__ float d_adst[NB*NN];
static __device__ float d_g0[NB*NN*NGD];
static __device__ float d_g1[NB*NN*NGD];
static __device__ float d_gwts[NB*NN*NHEAD];
static __device__ float d_q[NB*NHEAD*NHW*NHD];
static __device__ float d_k[NB*NHEAD*NHW*NHD];
static __device__ float d_v[NB*NHEAD*NHW*NHD];
static __device__ float d_ao[NB*NHW*NC];          // attention output [B, HW, C]

__device__ __forceinline__ float wsum(float v){
  #pragma unroll
  for (int o = 16; o; o >>= 1) v += __shfl_xor_sync(0xffffffffu, v, o);
  return v;
}
__device__ __forceinline__ float wmax(float v){
  #pragma unroll
  for (int o = 16; o; o >>= 1) v = fmaxf(v, __shfl_xor_sync(0xffffffffu, v, o));
  return v;
}
__device__ __forceinline__ unsigned f2tf32(float f){
  unsigned r; asm("cvt.rna.tf32.f32 %0, %1;" : "=r"(r) : "f"(f)); return r;
}
__device__ __forceinline__ void mma_tf32(float* d, const unsigned* a, unsigned b0, unsigned b1){
  asm volatile("mma.sync.aligned.m16n8k8.row.col.f32.tf32.tf32.f32 "
    "{%0,%1,%2,%3}, {%4,%5,%6,%7}, {%8,%9}, {%0,%1,%2,%3};\n"
    : "+f"(d[0]), "+f"(d[1]), "+f"(d[2]), "+f"(d[3])
    : "r"(a[0]), "r"(a[1]), "r"(a[2]), "r"(a[3]), "r"(b0), "r"(b1));
}

// ---------------- 1) transpose x [B,C,HW] -> xs [B,HW,C] ----------------
__global__ void transpose_kernel(const float* __restrict__ x){
  __shared__ float tile[32][33];
  int b = blockIdx.z;
  int hw0 = blockIdx.x * 32, c0 = blockIdx.y * 32;
  int tx = threadIdx.x, ty = threadIdx.y;
  #pragma unroll
  for (int i = 0; i < 4; i++)
    tile[ty + 8*i][tx] = x[((size_t)b*NC + (c0 + ty + 8*i))*NHW + hw0 + tx];
  __syncthreads();
  #pragma unroll
  for (int i = 0; i < 4; i++)
    d_xs[((size_t)b*NHW + (hw0 + ty + 8*i))*NC + c0 + tx] = tile[tx][ty + 8*i];
}

// ---------------- 2) variance (ddof=1) per (b,hw) ----------------
__global__ void importance_kernel(){
  int row = blockIdx.x * 8 + (threadIdx.x >> 5);
  int lane = threadIdx.x & 31;
  const float* p = d_xs + (size_t)row * NC;
  float v[8]; float s = 0.f;
  #pragma unroll
  for (int i = 0; i < 8; i++){ v[i] = p[lane + 32*i]; s += v[i]; }
  s = wsum(s);
  float mean = s * (1.f/256.f);
  float q = 0.f;
  #pragma unroll
  for (int i = 0; i < 8; i++){ float d = v[i] - mean; q += d*d; }
  q = wsum(q);
  if (lane == 0) d_imp[row] = q * (1.f/255.f);
}

// ---------------- 3) per-batch top-102 via bitonic sort ----------------
__global__ __launch_bounds__(1024) void topk_kernel(){
  __shared__ float key[1024];
  __shared__ int   idxv[1024];
  int b = blockIdx.x, tid = threadIdx.x;
  key[tid]  = d_imp[b*NHW + tid];
  idxv[tid] = tid;
  d_nodeof[b*NHW + tid] = -1;
  __syncthreads();
  for (int k = 2; k <= 1024; k <<= 1){
    for (int j = k >> 1; j > 0; j >>= 1){
      int ixj = tid ^ j;
      if (ixj > tid){
        bool desc = ((tid & k) == 0);
        float a = key[tid], bb = key[ixj];
        if (desc ? (a < bb) : (a > bb)){
          key[tid] = bb; key[ixj] = a;
          int t = idxv[tid]; idxv[tid] = idxv[ixj]; idxv[ixj] = t;
        }
      }
      __syncthreads();
    }
  }
  if (tid < NN){
    int src = idxv[tid];
    d_topidx[b*NN + tid] = src;
    d_nodeof[b*NHW + src] = tid;
  }
}

// ---------------- 4) gather node features ----------------
__global__ void gather_kernel(){
  int bi = blockIdx.x;
  int b = bi / NN;
  int src = d_topidx[bi];
  d_feats[(size_t)bi*NC + threadIdx.x] = d_xs[((size_t)b*NHW + src)*NC + threadIdx.x];
}

// ---------------- 5) row norms ----------------
__global__ void norm_kernel(){
  int row = blockIdx.x * 8 + (threadIdx.x >> 5);
  int lane = threadIdx.x & 31;
  const float* p = d_feats + (size_t)row * NC;
  float s = 0.f;
  #pragma unroll
  for (int i = 0; i < 8; i++){ float v = p[lane + 32*i]; s += v*v; }
  s = wsum(s);
  if (lane == 0) d_normv[row] = fmaxf(sqrtf(s), 1e-12f);
}

// ---------------- 6) cosine-sim adjacency (+self loops) ----------------
__global__ void adj_kernel(){
  int bi = blockIdx.x;
  int b = bi / NN, i = bi % NN;
  int warp = threadIdx.x >> 5, lane = threadIdx.x & 31;
  const float* fi = d_feats + (size_t)bi * NC;
  float ni = d_normv[bi];
  for (int j = warp; j < NN; j += 4){
    const float* fj = d_feats + ((size_t)b*NN + j) * NC;
    float s = 0.f;
    #pragma unroll
    for (int t = 0; t < 8; t++) s += fi[lane + 32*t] * fj[lane + 32*t];
    s = wsum(s);
    if (lane == 0){
      float sim = s / (ni * d_normv[b*NN + j]);
      d_adj[(size_t)bi*NN + j] = (unsigned char)((sim > 0.6f) || (j == i));
    }
  }
}

// ---------------- 7a) GAT: h = f @ W, plus attention coefficient terms ----------------
__global__ __launch_bounds__(64) void gat_h(int layer, const float* __restrict__ W,
    const float* __restrict__ aw_src, const float* __restrict__ aw_dst){
  __shared__ float sh[4];
  int bi = blockIdx.x;                 // 0..815 node
  int o = threadIdx.x;                 // 0..63 output
  int in_dim = layer ? NGD : NC;
  const float* f = (layer ? d_g0 : d_feats) + (size_t)bi * in_dim;
  float s = 0.f;
  for (int c = 0; c < in_dim; c += 4){
    float f0 = f[c], f1 = f[c+1], f2 = f[c+2], f3 = f[c+3];
    s += f0*W[(c  )*NGD+o];
    s += f1*W[(c+1)*NGD+o];
    s += f2*W[(c+2)*NGD+o];
    s += f3*W[(c+3)*NGD+o];
  }
  d_h[(size_t)bi*NGD + o] = s;
  float vs = wsum(s * aw_src[o]);
  float vd = wsum(s * aw_dst[o]);
  if ((o & 31) == 0){ sh[o>>5] = vs; sh[2 + (o>>5)] = vd; }
  __syncthreads();
  if (o == 0){ d_asrc[bi] = sh[0] + sh[1]; d_adst[bi] = sh[2] + sh[3]; }
}

// ---------------- 7b) GAT: softmax over neighbors + aggregate + relu ----------------
__global__ __launch_bounds__(128) void gat_agg(int layer, const float* __restrict__ bias){
  __shared__ float alpha[NN];
  __shared__ float red[4];
  __shared__ float part[128];
  int bi = blockIdx.x; int b = bi / NN;
  int tid = threadIdx.x;
  const unsigned char* arow = d_adj + (size_t)bi * NN;  // adj symmetric -> mask.T == mask
  float ad = d_adst[bi];
  float mx = -1e30f;
  for (int j = tid; j < NN; j += 128){
    float lg = ad + d_asrc[b*NN + j];
    lg = lg > 0.f ? lg : 0.2f*lg;
    if (!arow[j]) lg = -1e30f;
    alpha[j] = lg;
    mx = fmaxf(mx, lg);
  }
  mx = wmax(mx);
  if ((tid & 31) == 0) red[tid>>5] = mx;
  __syncthreads();
  mx = fmaxf(fmaxf(red[0], red[1]), fmaxf(red[2], red[3]));
  __syncthreads();
  float sum = 0.f;
  for (int j = tid; j < NN; j += 128){
    float e = __expf(alpha[j] - mx);
    alpha[j] = e;
    sum += e;
  }
  sum = wsum(sum);
  if ((tid & 31) == 0) red[tid>>5] = sum;
  __syncthreads();                       // also makes alpha writes visible
  float inv = 1.f / (red[0] + red[1] + red[2] + red[3]);
  int o = tid & 63, half = tid >> 6;
  float acc = 0.f;
  for (int j = half*51; j < half*51 + 51; j++)
    acc += alpha[j] * d_h[((size_t)b*NN + j)*NGD + o];
  part[tid] = acc;
  __syncthreads();
  if (tid < 64){
    float r = (part[tid] + part[tid + 64]) * inv + bias[tid];
    (layer ? d_g1 : d_g0)[(size_t)bi*NGD + tid] = fmaxf(r, 0.f);
  }
}

// ---------------- 8) graph -> attention gates ----------------
__global__ void g2a_kernel(const float* __restrict__ wg, const float* __restrict__ bg){
  int b = blockIdx.x, tid = threadIdx.x;
  for (int idx = tid; idx < NN*NHEAD; idx += 256){
    int i = idx >> 3, hh = idx & 7;
    const float* gr = d_g1 + ((size_t)b*NN + i) * NGD;
    float s = bg[hh];
    #pragma unroll
    for (int o = 0; o < NGD; o++) s += gr[o] * wg[hh*NGD + o];
    d_gwts[((size_t)b*NN + i)*NHEAD + hh] = 1.f / (1.f + __expf(-s));
  }
}

// ---------------- 9) QKV GEMM via tf32 mma: [8192,256] @ [256,768]^T ----------------
__global__ __launch_bounds__(256) void qkv_mma(const float* __restrict__ Wq){
  __shared__ unsigned As[128*20];
  __shared__ unsigned Bs[128*20];
  int tid = threadIdx.x, w = tid>>5, lane = tid&31;
  int g = lane>>2, t = lane&3;
  int mo = (w>>1)*32, no = (w&1)*64;
  int rowBase = blockIdx.y*128, colBase = blockIdx.x*128;
  float acc[2][8][4];
  #pragma unroll
  for (int mt=0;mt<2;mt++)
    #pragma unroll
    for (int nt=0;nt<8;nt++)
      #pragma unroll
      for (int r=0;r<4;r++) acc[mt][nt][r] = 0.f;

  for (int k0 = 0; k0 < 256; k0 += 16){
    __syncthreads();
    #pragma unroll
    for (int l = 0; l < 2; l++){
      int idx = tid + l*256;
      int r = idx>>2, c4 = (idx&3)<<2;
      float4 va = *(const float4*)&d_xs[(size_t)(rowBase + r)*256 + k0 + c4];
      *(uint4*)&As[r*20 + c4] = make_uint4(f2tf32(va.x), f2tf32(va.y), f2tf32(va.z), f2tf32(va.w));
      float4 vb = *(const float4*)&Wq[(size_t)(colBase + r)*256 + k0 + c4];
      *(uint4*)&Bs[r*20 + c4] = make_uint4(f2tf32(vb.x), f2tf32(vb.y), f2tf32(vb.z), f2tf32(vb.w));
    }
    __syncthreads();
    #pragma unroll
    for (int kc = 0; kc < 2; kc++){
      unsigned a[2][4];
      #pragma unroll
      for (int mt = 0; mt < 2; mt++){
        int r = mo + mt*16;
        a[mt][0] = As[(r+g  )*20 + kc*8 + t];
        a[mt][1] = As[(r+g+8)*20 + kc*8 + t];
        a[mt][2] = As[(r+g  )*20 + kc*8 + t + 4];
        a[mt][3] = As[(r+g+8)*20 + kc*8 + t + 4];
      }
      #pragma unroll
      for (int nt = 0; nt < 8; nt++){
        unsigned b0 = Bs[(no + nt*8 + g)*20 + kc*8 + t];
        unsigned b1 = Bs[(no + nt*8 + g)*20 + kc*8 + t + 4];
        mma_tf32(acc[0][nt], a[0], b0, b1);
        mma_tf32(acc[1][nt], a[1], b0, b1);
      }
    }
  }
  #pragma unroll
  for (int mt = 0; mt < 2; mt++){
    #pragma unroll
    for (int nt = 0; nt < 8; nt++){
      int col = colBase + no + nt*8 + t*2;
      int sct = col >> 8, hh = (col >> 5) & 7, dd = col & 31;
      float* base = (sct == 0) ? d_q : (sct == 1 ? d_k : d_v);
      int m1 = rowBase + mo + mt*16 + g;
      int b1 = m1 >> 10, hw1 = m1 & 1023;
      *(float2*)&base[(((size_t)(b1*8 + hh))*1024 + hw1)*32 + dd] =
          make_float2(acc[mt][nt][0], acc[mt][nt][1]);
      int m2 = m1 + 8;
      int b2 = m2 >> 10, hw2 = m2 & 1023;
      *(float2*)&base[(((size_t)(b2*8 + hh))*1024 + hw2)*32 + dd] =
          make_float2(acc[mt][nt][2], acc[mt][nt][3]);
    }
  }
}

// ---------------- 10) fused flash attention + graph modulation (tf32 mma) ----------------
#define KSS 36
#define VSS 40
__global__ __launch_bounds__(256) void attn_mma(){
  __shared__ unsigned Ks[64*KSS];
  __shared__ unsigned Vs[64*VSS];
  __shared__ float kg[64]; __shared__ int kn[64];
  __shared__ float qg[128]; __shared__ int qn[128];

  int bh = blockIdx.x, b = bh>>3, h = bh&7;
  int q0 = blockIdx.y << 7;        // 128 q rows per block
  int tid = threadIdx.x, w = tid>>5, lane = tid&31;
  int g = lane>>2, t = lane&3;

  // Q fragments (scale folded in), rows w*16+g / +8, k-chunks 0..3
  unsigned aQ[4][4];
  {
    const float scale = 0.17677669529663687f;   // 1/sqrt(32)
    const float* Qb = d_q + ((size_t)bh*NHW + q0 + w*16)*NHD;
    #pragma unroll
    for (int kc = 0; kc < 4; kc++){
      aQ[kc][0] = f2tf32(Qb[(g  )*NHD + kc*8 + t    ] * scale);
      aQ[kc][1] = f2tf32(Qb[(g+8)*NHD + kc*8 + t    ] * scale);
      aQ[kc][2] = f2tf32(Qb[(g  )*NHD + kc*8 + t + 4] * scale);
      aQ[kc][3] = f2tf32(Qb[(g+8)*NHD + kc*8 + t + 4] * scale);
    }
  }
  if (tid < 128){
    int iq = d_nodeof[b*NHW + q0 + tid];
    qn[tid] = iq;
    qg[tid] = (iq >= 0) ? d_gwts[((size_t)b*NN + iq)*NHEAD + h] : 0.f;
  }

  const unsigned char* adjb = d_adj + (size_t)b * NN * NN;
  int r1 = w*16 + g, r2 = r1 + 8;

  float m1 = -1e30f, m2 = -1e30f, l1 = 0.f, l2 = 0.f;
  float o[4][4];
  #pragma unroll
  for (int dt = 0; dt < 4; dt++)
    #pragma unroll
    for (int r = 0; r < 4; r++) o[dt][r] = 0.f;

  for (int kt = 0; kt < 16; kt++){
    __syncthreads();
    const float* Kb = d_k + ((size_t)bh*NHW + kt*64)*NHD;
    const float* Vb = d_v + ((size_t)bh*NHW + kt*64)*NHD;
    #pragma unroll
    for (int l = 0; l < 2; l++){
      int idx = tid + l*256;
      int r = idx>>3, c4 = (idx&7)<<2;
      float4 kv = *(const float4*)(Kb + r*NHD + c4);
      *(uint4*)&Ks[r*KSS + c4] = make_uint4(f2tf32(kv.x), f2tf32(kv.y), f2tf32(kv.z), f2tf32(kv.w));
      float4 vv = *(const float4*)(Vb + r*NHD + c4);
      *(uint4*)&Vs[r*VSS + c4] = make_uint4(f2tf32(vv.x), f2tf32(vv.y), f2tf32(vv.z), f2tf32(vv.w));
    }
    if (tid < 64){
      int ik = d_nodeof[b*NHW + kt*64 + tid];
      kn[tid] = ik;
      kg[tid] = (ik >= 0) ? d_gwts[((size_t)b*NN + ik)*NHEAD + h] : 0.f;
    }
    __syncthreads();

    // S = Q K^T : per-warp 16x64 via 4 kchunks x 8 ntiles
    float s[8][4];
    #pragma unroll
    for (int nt = 0; nt < 8; nt++)
      #pragma unroll
      for (int r = 0; r < 4; r++) s[nt][r] = 0.f;
    #pragma unroll
    for (int kc = 0; kc < 4; kc++){
      #pragma unroll
      for (int nt = 0; nt < 8; nt++){
        unsigned b0 = Ks[(nt*8 + g)*KSS + kc*8 + t];
        unsigned b1 = Ks[(nt*8 + g)*KSS + kc*8 + t + 4];
        mma_tf32(s[nt], aQ[kc], b0, b1);
      }
    }

    // graph modulation
    int iq1 = qn[r1], iq2 = qn[r2];
    if (iq1 >= 0 || iq2 >= 0){
      float qg1 = qg[r1], qg2 = qg[r2];
      #pragma unroll
      for (int nt = 0; nt < 8; nt++){
        int c = nt*8 + t*2;
        int k0 = kn[c], k1 = kn[c+1];
        if (iq1 >= 0){
          if (k0 >= 0 && adjb[iq1*NN + k0]) s[nt][0] += qg1 * kg[c];
          if (k1 >= 0 && adjb[iq1*NN + k1]) s[nt][1] += qg1 * kg[c+1];
        }
        if (iq2 >= 0){
          if (k0 >= 0 && adjb[iq2*NN + k0]) s[nt][2] += qg2 * kg[c];
          if (k1 >= 0 && adjb[iq2*NN + k1]) s[nt][3] += qg2 * kg[c+1];
        }
      }
    }

    // online softmax (rows fully owned by the quad: xor 1,2)
    float mx1 = -1e30f, mx2 = -1e30f;
    #pragma unroll
    for (int nt = 0; nt < 8; nt++){
      mx1 = fmaxf(mx1, fmaxf(s[nt][0], s[nt][1]));
      mx2 = fmaxf(mx2, fmaxf(s[nt][2], s[nt][3]));
    }
    mx1 = fmaxf(mx1, __shfl_xor_sync(0xffffffffu, mx1, 1));
    mx1 = fmaxf(mx1, __shfl_xor_sync(0xffffffffu, mx1, 2));
    mx2 = fmaxf(mx2, __shfl_xor_sync(0xffffffffu, mx2, 1));
    mx2 = fmaxf(mx2, __shfl_xor_sync(0xffffffffu, mx2, 2));
    float mn1 = fmaxf(m1, mx1), mn2 = fmaxf(m2, mx2);
    float f1 = __expf(m1 - mn1), f2v = __expf(m2 - mn2);
    float sm1 = 0.f, sm2 = 0.f;
    #pragma unroll
    for (int nt = 0; nt < 8; nt++){
      s[nt][0] = __expf(s[nt][0] - mn1); sm1 += s[nt][0];
      s[nt][1] = __expf(s[nt][1] - mn1); sm1 += s[nt][1];
      s[nt][2] = __expf(s[nt][2] - mn2); sm2 += s[nt][2];
      s[nt][3] = __expf(s[nt][3] - mn2); sm2 += s[nt][3];
    }
    sm1 += __shfl_xor_sync(0xffffffffu, sm1, 1);
    sm1 += __shfl_xor_sync(0xffffffffu, sm1, 2);
    sm2 += __shfl_xor_sync(0xffffffffu, sm2, 1);
    sm2 += __shfl_xor_sync(0xffffffffu, sm2, 2);
    l1 = l1*f1 + sm1; l2 = l2*f2v + sm2;
    m1 = mn1; m2 = mn2;
    #pragma unroll
    for (int dt = 0; dt < 4; dt++){
      o[dt][0] *= f1;  o[dt][1] *= f1;
      o[dt][2] *= f2v; o[dt][3] *= f2v;
    }

    // O += P V : re-layout P (C-frag) -> A-frag via shuffles, then mma
    int srcA = (lane & ~3) | (t >> 1);
    int srcB = srcA + 2;
    bool odd = (t & 1);
    #pragma unroll
    for (int kc = 0; kc < 8; kc++){
      float q00 = __shfl_sync(0xffffffffu, s[kc][0], srcA);
      float q01 = __shfl_sync(0xffffffffu, s[kc][1], srcA);
      float q20 = __shfl_sync(0xffffffffu, s[kc][2], srcA);
      float q21 = __shfl_sync(0xffffffffu, s[kc][3], srcA);
      float u00 = __shfl_sync(0xffffffffu, s[kc][0], srcB);
      float u01 = __shfl_sync(0xffffffffu, s[kc][1], srcB);
      float u20 = __shfl_sync(0xffffffffu, s[kc][2], srcB);
      float u21 = __shfl_sync(0xffffffffu, s[kc][3], srcB);
      unsigned aP[4];
      aP[0] = f2tf32(odd ? q01 : q00);
      aP[1] = f2tf32(odd ? q21 : q20);
      aP[2] = f2tf32(odd ? u01 : u00);
      aP[3] = f2tf32(odd ? u21 : u20);
      #pragma unroll
      for (int dt = 0; dt < 4; dt++){
        unsigned b0 = Vs[(kc*8 + t    )*VSS + dt*8 + g];
        unsigned b1 = Vs[(kc*8 + t + 4)*VSS + dt*8 + g];
        mma_tf32(o[dt], aP, b0, b1);
      }
    }
  }

  // epilogue
  float i1 = 1.f / l1, i2 = 1.f / l2;
  float* dst1 = d_ao + ((size_t)b*NHW + q0 + r1)*NC + h*NHD;
  float* dst2 = dst1 + 8*NC;
  #pragma unroll
  for (int dt = 0; dt < 4; dt++){
    int col = dt*8 + t*2;
    *(float2*)&dst1[col] = make_float2(o[dt][0]*i1, o[dt][1]*i1);
    *(float2*)&dst2[col] = make_float2(o[dt][2]*i2, o[dt][3]*i2);
  }
}

// ---------------- 11) proj GEMM via tf32 mma + bias + transposed store ----------------
__global__ __launch_bounds__(256) void proj_mma(const float* __restrict__ Wp,
    const float* __restrict__ bias, float* __restrict__ out){
  __shared__ unsigned As[128*20];
  __shared__ unsigned Bs[128*20];
  int tid = threadIdx.x, w = tid>>5, lane = tid&31;
  int g = lane>>2, t = lane&3;
  int mo = (w>>1)*32, no = (w&1)*64;
  int rowBase = blockIdx.y*128, colBase = blockIdx.x*128;
  float acc[2][8][4];
  #pragma unroll
  for (int mt=0;mt<2;mt++)
    #pragma unroll
    for (int nt=0;nt<8;nt++)
      #pragma unroll
      for (int r=0;r<4;r++) acc[mt][nt][r] = 0.f;

  for (int k0 = 0; k0 < 256; k0 += 16){
    __syncthreads();
    #pragma unroll
    for (int l = 0; l < 2; l++){
      int idx = tid + l*256;
      int r = idx>>2, c4 = (idx&3)<<2;
      float4 va = *(const float4*)&d_ao[(size_t)(rowBase + r)*256 + k0 + c4];
      *(uint4*)&As[r*20 + c4] = make_uint4(f2tf32(va.x), f2tf32(va.y), f2tf32(va.z), f2tf32(va.w));
      float4 vb = *(const float4*)&Wp[(size_t)(colBase + r)*256 + k0 + c4];
      *(uint4*)&Bs[r*20 + c4] = make_uint4(f2tf32(vb.x), f2tf32(vb.y), f2tf32(vb.z), f2tf32(vb.w));
    }
    __syncthreads();
    #pragma unroll
    for (int kc = 0; kc < 2; kc++){
      unsigned a[2][4];
      #pragma unroll
      for (int mt = 0; mt < 2; mt++){
        int r = mo + mt*16;
        a[mt][0] = As[(r+g  )*20 + kc*8 + t];
        a[mt][1] = As[(r+g+8)*20 + kc*8 + t];
        a[mt][2] = As[(r+g  )*20 + kc*8 + t + 4];
        a[mt][3] = As[(r+g+8)*20 + kc*8 + t + 4];
      }
      #pragma unroll
      for (int nt = 0; nt < 8; nt++){
        unsigned b0 = Bs[(no + nt*8 + g)*20 + kc*8 + t];
        unsigned b1 = Bs[(no + nt*8 + g)*20 + kc*8 + t + 4];
        mma_tf32(acc[0][nt], a[0], b0, b1);
        mma_tf32(acc[1][nt], a[1], b0, b1);
      }
    }
  }
  #pragma unroll
  for (int mt = 0; mt < 2; mt++){
    #pragma unroll
    for (int nt = 0; nt < 8; nt++){
      int col = colBase + no + nt*8 + t*2;
      float bc0 = bias[col], bc1 = bias[col+1];
      int m1 = rowBase + mo + mt*16 + g;
      int b1 = m1 >> 10, hw1 = m1 & 1023;
      out[((size_t)(b1*NC + col    ))*NHW + hw1] = acc[mt][nt][0] + bc0;
      out[((size_t)(b1*NC + col + 1))*NHW + hw1] = acc[mt][nt][1] + bc1;
      int m2 = m1 + 8;
      int b2 = m2 >> 10, hw2 = m2 & 1023;
      out[((size_t)(b2*NC + col    ))*NHW + hw2] = acc[mt][nt][2] + bc0;
      out[((size_t)(b2*NC + col + 1))*NHW + hw2] = acc[mt][nt][3] + bc1;
    }
  }
}

// ---------------- launch ----------------
extern "C" void kernel_launch(void* const* d_in, const int* in_sizes, int n_in,
                              void* d_out, int out_size){
  (void)in_sizes; (void)n_in; (void)out_size;
  const float* x      = (const float*)d_in[0];
  const float* w_qkv  = (const float*)d_in[1];
  const float* w_proj = (const float*)d_in[2];
  const float* b_proj = (const float*)d_in[3];
  const float* g0W    = (const float*)d_in[4];
  const float* g0s    = (const float*)d_in[5];
  const float* g0d    = (const float*)d_in[6];
  const float* g0b    = (const float*)d_in[7];
  const float* g1W    = (const float*)d_in[8];
  const float* g1s    = (const float*)d_in[9];
  const float* g1d    = (const float*)d_in[10];
  const float* g1b    = (const float*)d_in[11];
  const float* wg2a   = (const float*)d_in[12];
  const float* bg2a   = (const float*)d_in[13];
  float* out = (float*)d_out;

  transpose_kernel<<<dim3(32, 8, 8), dim3(32, 8)>>>(x);
  importance_kernel<<<1024, 256>>>();
  topk_kernel<<<8, 1024>>>();
  gather_kernel<<<816, 256>>>();
  norm_kernel<<<102, 256>>>();
  adj_kernel<<<816, 128>>>();
  gat_h<<<816, 64>>>(0, g0W, g0s, g0d);
  gat_agg<<<816, 128>>>(0, g0b);
  gat_h<<<816, 64>>>(1, g1W, g1s, g1d);
  gat_agg<<<816, 128>>>(1, g1b);
  g2a_kernel<<<8, 256>>>(wg2a, bg2a);
  qkv_mma<<<dim3(6, 64), 256>>>(w_qkv);
  attn_mma<<<dim3(64, 8), 256>>>();
  proj_mma<<<dim3(2, 64), 256>>>(w_proj, b_proj, out);
}